// round 5
// baseline (speedup 1.0000x reference)
#include <cuda_runtime.h>
#include <cuda_bf16.h>
#include <cstdint>

#define NNODES 65536
#define NEDGES 262144

// ============================ device scratch ============================
__device__ __align__(256) __nv_bfloat16 g_xb   [NNODES * 256];
__device__ __align__(256) __nv_bfloat16 g_hnode[NNODES * 128];
__device__ __align__(256) __nv_bfloat16 g_grow [NNODES * 256];
__device__ __align__(256) __nv_bfloat16 g_gcol [NNODES * 256];
__device__ __align__(256) __nv_bfloat16 g_eab  [NEDGES * 64];
__device__ __align__(256) __nv_bfloat16 g_h0   [(size_t)NEDGES * 256];  // ea@W0c + b0 -> combined
// weight images, [NOUT][K] bf16 row-major (k contiguous) == B col-major for mma row.col
__device__ __align__(256) __nv_bfloat16 g_Bx [128 * 256];
__device__ __align__(256) __nv_bfloat16 g_B0a[256 * 128];
__device__ __align__(256) __nv_bfloat16 g_B0b[256 * 128];
__device__ __align__(256) __nv_bfloat16 g_B0c[256 * 64];
__device__ __align__(256) __nv_bfloat16 g_Bm [8][256 * 256];
__device__ int g_idx64;

// ============================ PTX helpers (base PTX only) ============================
__device__ __forceinline__ uint32_t smem_u32(const void* p) {
    uint32_t a;
    asm("{ .reg .u64 t; cvta.to.shared.u64 t, %1; cvt.u32.u64 %0, t; }" : "=r"(a) : "l"(p));
    return a;
}
__device__ __forceinline__ void cp16(uint32_t dst, const void* src) {
    asm volatile("cp.async.cg.shared.global [%0], [%1], 16;" :: "r"(dst), "l"(src));
}
__device__ __forceinline__ void cp_commit() {
    asm volatile("cp.async.commit_group;" ::: "memory");
}
template <int N>
__device__ __forceinline__ void cp_wait() {
    asm volatile("cp.async.wait_group %0;" :: "n"(N) : "memory");
}
__device__ __forceinline__ void ldm_x4(uint32_t* r, uint32_t addr) {
    asm volatile("ldmatrix.sync.aligned.m8n8.x4.shared.b16 {%0,%1,%2,%3}, [%4];"
                 : "=r"(r[0]), "=r"(r[1]), "=r"(r[2]), "=r"(r[3]) : "r"(addr));
}
__device__ __forceinline__ void ldm_x2(uint32_t* r, uint32_t addr) {
    asm volatile("ldmatrix.sync.aligned.m8n8.x2.shared.b16 {%0,%1}, [%2];"
                 : "=r"(r[0]), "=r"(r[1]) : "r"(addr));
}
__device__ __forceinline__ void mma_bf16(float* c, const uint32_t* a, const uint32_t* b) {
    asm volatile(
        "mma.sync.aligned.m16n8k16.row.col.f32.bf16.bf16.f32 "
        "{%0,%1,%2,%3}, {%4,%5,%6,%7}, {%8,%9}, {%0,%1,%2,%3};"
        : "+f"(c[0]), "+f"(c[1]), "+f"(c[2]), "+f"(c[3])
        : "r"(a[0]), "r"(a[1]), "r"(a[2]), "r"(a[3]), "r"(b[0]), "r"(b[1]));
}

// ============================ prep: everything in one launch ============================
__global__ void prep_everything(const float* __restrict__ x, const float* __restrict__ ea,
                                const float* __restrict__ Wx, const float* __restrict__ W0,
                                const float* __restrict__ Wm, const unsigned* __restrict__ ei) {
    if (blockIdx.x == 0 && threadIdx.x == 0) {
        int is64 = 1;
        for (int i = 0; i < 512; i++)
            if (ei[2 * i + 1] != 0u) { is64 = 0; break; }
        g_idx64 = is64;
    }
    const int stride = gridDim.x * blockDim.x;
    const int tid0 = blockIdx.x * blockDim.x + threadIdx.x;
    // x -> bf16
    for (int i = tid0; i < NNODES * 256; i += stride)
        g_xb[i] = __float2bfloat16(x[i]);
    // edge_attr -> [E,64] padded bf16
    for (int i = tid0; i < NEDGES * 64; i += stride) {
        int e = i >> 6, k = i & 63;
        g_eab[i] = __float2bfloat16(k < 16 ? ea[e * 16 + k] : 0.f);
    }
    // weight images
    const int total = 32768 + 32768 + 32768 + 16384 + 524288;
    for (int i = tid0; i < total; i += stride) {
        if (i < 32768) {                                   // Bx: [128][256]
            int n = i >> 8, k = i & 255;
            g_Bx[i] = __float2bfloat16(Wx[k * 128 + n]);
        } else if (i < 65536) {                            // B0a: [256][128]
            int j = i - 32768;
            int n = j >> 7, k = j & 127;
            g_B0a[j] = __float2bfloat16(W0[k * 256 + n]);
        } else if (i < 98304) {                            // B0b: [256][128]
            int j = i - 65536;
            int n = j >> 7, k = j & 127;
            g_B0b[j] = __float2bfloat16(W0[(128 + k) * 256 + n]);
        } else if (i < 114688) {                           // B0c: [256][64]
            int j = i - 98304;
            int n = j >> 6, k = j & 63;
            g_B0c[j] = __float2bfloat16(k < 16 ? W0[(256 + k) * 256 + n] : 0.f);
        } else {                                           // Bm: 8 x [256][256]
            int j = i - 114688;
            int L = j >> 16, r = j & 65535;
            int n = r >> 8, k = r & 255;
            g_Bm[L][r] = __float2bfloat16(Wm[(size_t)L * 65536 + k * 256 + n]);
        }
    }
}

// ============================ generic HMMA GEMM (prep stages) ============================
template <int K, int NOUT, bool LEAKY, bool HASBIAS, bool DUAL>
__global__ void __launch_bounds__(256)
gemm_mma(const __nv_bfloat16* __restrict__ A, const __nv_bfloat16* __restrict__ Bin,
         const __nv_bfloat16* __restrict__ B2, const float* __restrict__ bias,
         __nv_bfloat16* __restrict__ Out1, __nv_bfloat16* __restrict__ Out2) {
    static_assert(K % 64 == 0, "");
    constexpr int KT = K / 64;
    extern __shared__ char smem[];
    const uint32_t sb = smem_u32(smem);
    constexpr uint32_t STAGE = 32768, BOFF = 16384;

    const __nv_bfloat16* B = (DUAL && blockIdx.z) ? B2 : Bin;
    __nv_bfloat16* Out = (DUAL && blockIdx.z) ? Out2 : Out1;

    const int tid = threadIdx.x;
    const int lane = tid & 31, warp = tid >> 5;
    const int warp_m = warp & 1;
    const int warp_n = warp >> 1;
    const size_t m0 = (size_t)blockIdx.x * 128;
    const int n0 = blockIdx.y * 128;

    float acc[4][4][4];
    #pragma unroll
    for (int i = 0; i < 4; i++)
        #pragma unroll
        for (int j = 0; j < 4; j++)
            #pragma unroll
            for (int q = 0; q < 4; q++) acc[i][j][q] = 0.f;

    auto load_stage = [&](int stage, int kt) {
        const uint32_t base = sb + stage * STAGE;
        #pragma unroll
        for (int i = 0; i < 4; i++) {
            int idx = tid + i * 256;
            int r = idx >> 3, c8 = idx & 7;
            uint32_t dst = base + r * 128 + (((c8 ^ (r & 7))) << 4);
            cp16(dst, A + (m0 + r) * K + kt * 64 + c8 * 8);
        }
        #pragma unroll
        for (int i = 0; i < 4; i++) {
            int idx = tid + i * 256;
            int r = idx >> 3, c8 = idx & 7;
            uint32_t dst = base + BOFF + r * 128 + (((c8 ^ (r & 7))) << 4);
            cp16(dst, B + (size_t)(n0 + r) * K + kt * 64 + c8 * 8);
        }
    };

    load_stage(0, 0);
    cp_commit();

    for (int kt = 0; kt < KT; kt++) {
        if (kt + 1 < KT) { load_stage((kt + 1) & 1, kt + 1); cp_commit(); cp_wait<1>(); }
        else             { cp_wait<0>(); }
        __syncthreads();

        const uint32_t abase = sb + (kt & 1) * STAGE;
        const uint32_t bbase = abase + BOFF;
        #pragma unroll
        for (int ks = 0; ks < 4; ks++) {
            uint32_t af[4][4];
            #pragma unroll
            for (int mi = 0; mi < 4; mi++) {
                int r = warp_m * 64 + mi * 16 + (lane & 15);
                int c8 = ks * 2 + (lane >> 4);
                ldm_x4(af[mi], abase + r * 128 + ((c8 ^ (r & 7)) << 4));
            }
            uint32_t bf2[4][2];
            #pragma unroll
            for (int ni = 0; ni < 4; ni++) {
                int r = warp_n * 32 + ni * 8 + (lane & 7);
                int c8 = ks * 2 + ((lane >> 3) & 1);
                ldm_x2(bf2[ni], bbase + r * 128 + ((c8 ^ (r & 7)) << 4));
            }
            #pragma unroll
            for (int mi = 0; mi < 4; mi++)
                #pragma unroll
                for (int ni = 0; ni < 4; ni++)
                    mma_bf16(acc[mi][ni], af[mi], bf2[ni]);
        }
        __syncthreads();
    }

    const int g = lane >> 2;
    #pragma unroll
    for (int ni = 0; ni < 4; ni++) {
        const int col = n0 + warp_n * 32 + ni * 8 + ((lane & 3) << 1);
        float bb0 = 0.f, bb1 = 0.f;
        if (HASBIAS) { bb0 = __ldg(bias + col); bb1 = __ldg(bias + col + 1); }
        #pragma unroll
        for (int mi = 0; mi < 4; mi++) {
            const size_t r0 = m0 + warp_m * 64 + mi * 16 + g;
            float v0 = acc[mi][ni][0] + bb0, v1 = acc[mi][ni][1] + bb1;
            float v2 = acc[mi][ni][2] + bb0, v3 = acc[mi][ni][3] + bb1;
            if (LEAKY) {
                v0 = v0 >= 0.f ? v0 : 0.01f * v0;  v1 = v1 >= 0.f ? v1 : 0.01f * v1;
                v2 = v2 >= 0.f ? v2 : 0.01f * v2;  v3 = v3 >= 0.f ? v3 : 0.01f * v3;
            }
            __nv_bfloat162 p0 = __floats2bfloat162_rn(v0, v1);
            __nv_bfloat162 p1 = __floats2bfloat162_rn(v2, v3);
            *(uint32_t*)(Out + r0 * NOUT + col)       = *(uint32_t*)&p0;
            *(uint32_t*)(Out + (r0 + 8) * NOUT + col) = *(uint32_t*)&p1;
        }
    }
}

// ============================ gather + combine ============================
// h0[e] = leaky(h0[e] (= ea@W0c + b0) + grow[row[e]] + gcol[col[e]])
__global__ void gather_combine(const int* __restrict__ ei,
                               const __nv_bfloat16* __restrict__ gr,
                               const __nv_bfloat16* __restrict__ gc,
                               __nv_bfloat16* __restrict__ h0) {
    __shared__ int srow[64], scol[64];
    const int t = threadIdx.x;
    const long e0 = (long)blockIdx.x * 64;
    const int is64 = g_idx64;
    if (t < 64) {
        long e = e0 + t;
        if (is64) { srow[t] = ei[2 * e]; scol[t] = ei[2 * (NEDGES + e)]; }
        else      { srow[t] = ei[e];     scol[t] = ei[NEDGES + e]; }
    }
    __syncthreads();
    const int cp = t & 127;
    const int eo = t >> 7;
    for (int i = eo; i < 64; i += 2) {
        long e = e0 + i;
        const __nv_bfloat162* grp = (const __nv_bfloat162*)(gr + (size_t)srow[i] * 256);
        const __nv_bfloat162* gcp = (const __nv_bfloat162*)(gc + (size_t)scol[i] * 256);
        __nv_bfloat162* hp = (__nv_bfloat162*)(h0 + (size_t)e * 256);
        float2 a = __bfloat1622float2(hp[cp]);
        float2 b = __bfloat1622float2(grp[cp]);
        float2 c = __bfloat1622float2(gcp[cp]);
        float v0 = a.x + b.x + c.x, v1 = a.y + b.y + c.y;
        v0 = v0 >= 0.f ? v0 : 0.01f * v0;
        v1 = v1 >= 0.f ? v1 : 0.01f * v1;
        hp[cp] = __floats2bfloat162_rn(v0, v1);
    }
}

// ============================ fused 8 mid layers + head (N-quarter-major) ============================
// CTA = 128 edges, 8 warps, warp tile 16(M) x 256(N). Activations chained in registers.
// Weight slots: (layer, N-quarter) = [64 N][256 K] bf16 = 32KB, row pitch 512B, 3-region ring.
// A-tile occupies ring regions 0-1 during the prologue only.
__global__ void __launch_bounds__(256, 1)
fused_mid(const __nv_bfloat16* __restrict__ h0, const __nv_bfloat16* __restrict__ Bm,
          const float* __restrict__ bm, const float* __restrict__ Wl,
          const float* __restrict__ bl, float* __restrict__ out) {
    extern __shared__ char smem[];
    const uint32_t sb = smem_u32(smem);
    constexpr uint32_t PARAM = 98304;                 // ring: 3 x 32KB at [0, 98304)
    float* sbias = (float*)(smem + PARAM);            // 8KB  (8 x 256 fp32)
    float* sWl   = (float*)(smem + PARAM + 8192);     // 3KB  (256 x 3 fp32)
    float* sbl   = (float*)(smem + PARAM + 8192 + 3072);

    const int tid = threadIdx.x, lane = tid & 31, warp = tid >> 5;
    const size_t m0 = (size_t)blockIdx.x * 128;

    for (int i = tid; i < 2048; i += 256) sbias[i] = bm[i];
    for (int i = tid; i < 768; i += 256) sWl[i] = Wl[i];
    if (tid < 3) sbl[tid] = bl[tid];

    // slot loader: slot index s (0..31) -> layer s>>2, N-quarter s&3, ring region (s+2)%3
    auto loadSlot = [&](int s) {
        const uint32_t base = sb + (uint32_t)((s + 2) % 3) * 32768u;
        const __nv_bfloat16* src = Bm + (size_t)(s >> 2) * 65536 + (size_t)(s & 3) * 64 * 256;
        #pragma unroll
        for (int i = 0; i < 8; i++) {
            int idx = tid + i * 256;           // 0..2047 16B units
            int r = idx >> 5, u = idx & 31;    // r: N row 0..63, u: 16B unit in 512B row
            int kc = u >> 3, c8 = u & 7;
            cp16(base + r * 512 + kc * 128 + ((c8 ^ (r & 7)) << 4),
                 src + (size_t)r * 256 + u * 8);
        }
    };

    // A tile (h0, 128x256 bf16 = 64KB) -> ring regions 0-1 as 4 chunks [128][64] pitch 128B
    #pragma unroll
    for (int i = 0; i < 16; i++) {
        int idx = tid + i * 256;               // 0..4095 16B units
        int r = idx >> 5, u = idx & 31;
        int kc = u >> 3, c8 = u & 7;
        cp16(sb + kc * 16384 + r * 128 + ((c8 ^ (r & 7)) << 4),
             h0 + (m0 + r) * 256 + u * 8);
    }
    cp_commit();                 // G0 = A
    loadSlot(0); cp_commit();    // G1 = slot 0 (region 2)
    cp_wait<1>();                // A done
    __syncthreads();

    // ldmatrix A -> packed activation fragments pa[32][2]
    uint32_t pa[32][2];
    #pragma unroll
    for (int s = 0; s < 16; s++) {
        int rr = warp * 16 + (lane & 15);
        int cc = (s & 3) * 2 + (lane >> 4);
        uint32_t f[4];
        ldm_x4(f, sb + (s >> 2) * 16384 + rr * 128 + ((cc ^ (rr & 7)) << 4));
        pa[2 * s][0] = f[0]; pa[2 * s][1] = f[1];
        pa[2 * s + 1][0] = f[2]; pa[2 * s + 1][1] = f[3];
    }
    __syncthreads();             // all warps done reading regions 0-1
    loadSlot(1); cp_commit();    // G2 -> region 0
    loadSlot(2); cp_commit();    // G3 -> region 1

    uint32_t pn[32][2];
    const int j = lane & 3;
    const int rr_lo = ((lane >> 4) << 3) + (lane & 7);

    for (int s = 0; s < 32; s++) {
        const int nq = s & 3, l = s >> 2;
        cp_wait<2>();
        __syncthreads();
        const uint32_t slot = sb + (uint32_t)((s + 2) % 3) * 32768u;

        float acc[8][4];     // 16 rows x 64 cols quarter; idx = np*2 + nt
        #pragma unroll
        for (int q = 0; q < 8; q++) {
            float2 bb = *(const float2*)(sbias + (l << 8) + nq * 64 + q * 8 + 2 * j);
            acc[q][0] = bb.x; acc[q][1] = bb.y; acc[q][2] = bb.x; acc[q][3] = bb.y;
        }
        #pragma unroll
        for (int kh = 0; kh < 4; kh++) {
            #pragma unroll
            for (int ksl = 0; ksl < 4; ksl++) {
                const int ai = kh * 8 + ksl * 2;
                uint32_t a[4] = {pa[ai][0], pa[ai][1], pa[ai + 1][0], pa[ai + 1][1]};
                const int cc = ksl * 2 + ((lane >> 3) & 1);
                #pragma unroll
                for (int np = 0; np < 4; np++) {
                    int rr = np * 16 + rr_lo;
                    uint32_t bf[4];
                    ldm_x4(bf, slot + rr * 512 + kh * 128 + ((cc ^ (rr & 7)) << 4));
                    mma_bf16(acc[np * 2], a, bf);
                    mma_bf16(acc[np * 2 + 1], a, bf + 2);
                }
            }
        }
        __syncthreads();                       // region free for reuse
        if (s + 3 < 32) loadSlot(s + 3);
        cp_commit();                           // commit every iter (group count stays aligned)

        // leaky + pack this quarter into pn
        #pragma unroll
        for (int q = 0; q < 8; q++) {
            float v0 = acc[q][0], v1 = acc[q][1], v2 = acc[q][2], v3 = acc[q][3];
            v0 = v0 >= 0.f ? v0 : 0.01f * v0;  v1 = v1 >= 0.f ? v1 : 0.01f * v1;
            v2 = v2 >= 0.f ? v2 : 0.01f * v2;  v3 = v3 >= 0.f ? v3 : 0.01f * v3;
            __nv_bfloat162 p0 = __floats2bfloat162_rn(v0, v1);
            __nv_bfloat162 p1 = __floats2bfloat162_rn(v2, v3);
            pn[8 * nq + q][0] = *(uint32_t*)&p0;
            pn[8 * nq + q][1] = *(uint32_t*)&p1;
        }
        if (nq == 3) {
            #pragma unroll
            for (int t = 0; t < 32; t++) { pa[t][0] = pn[t][0]; pa[t][1] = pn[t][1]; }
        }
    }

    // ---- fused head: logits = h @ Wlast + blast, then log_softmax ----
    float a3[2][3] = {{0.f, 0.f, 0.f}, {0.f, 0.f, 0.f}};
    #pragma unroll
    for (int t = 0; t < 32; t++) {
        float2 x = __bfloat1622float2(*(__nv_bfloat162*)&pa[t][0]);
        float2 y = __bfloat1622float2(*(__nv_bfloat162*)&pa[t][1]);
        const int c0 = 8 * t + 2 * j;
        float w00 = sWl[c0 * 3 + 0], w01 = sWl[c0 * 3 + 1], w02 = sWl[c0 * 3 + 2];
        float w10 = sWl[c0 * 3 + 3], w11 = sWl[c0 * 3 + 4], w12 = sWl[c0 * 3 + 5];
        a3[0][0] += x.x * w00 + x.y * w10;
        a3[0][1] += x.x * w01 + x.y * w11;
        a3[0][2] += x.x * w02 + x.y * w12;
        a3[1][0] += y.x * w00 + y.y * w10;
        a3[1][1] += y.x * w01 + y.y * w11;
        a3[1][2] += y.x * w02 + y.y * w12;
    }
    #pragma unroll
    for (int off = 1; off <= 2; off <<= 1) {
        #pragma unroll
        for (int r = 0; r < 2; r++)
            #pragma unroll
            for (int c = 0; c < 3; c++)
                a3[r][c] += __shfl_xor_sync(0xFFFFFFFFu, a3[r][c], off);
    }
    if (j == 0) {
        const int g = lane >> 2;
        const float bb0 = sbl[0], bb1 = sbl[1], bb2 = sbl[2];
        #pragma unroll
        for (int r = 0; r < 2; r++) {
            size_t e = m0 + warp * 16 + g + 8 * r;
            float l0 = a3[r][0] + bb0, l1 = a3[r][1] + bb1, l2 = a3[r][2] + bb2;
            float m = fmaxf(l0, fmaxf(l1, l2));
            float ls = m + logf(expf(l0 - m) + expf(l1 - m) + expf(l2 - m));
            out[e * 3 + 0] = l0 - ls;
            out[e * 3 + 1] = l1 - ls;
            out[e * 3 + 2] = l2 - ls;
        }
    }
}

// ============================ host ============================
extern "C" void kernel_launch(void* const* d_in, const int* in_sizes, int n_in,
                              void* d_out, int out_size) {
    const float* x  = (const float*)d_in[0];
    const int*   ei = (const int*)d_in[1];
    const float* ea = (const float*)d_in[2];
    const float* Wx = (const float*)d_in[3];
    const float* bx = (const float*)d_in[4];
    const float* W0 = (const float*)d_in[5];
    const float* b0 = (const float*)d_in[6];
    const float* Wm = (const float*)d_in[7];
    const float* bm = (const float*)d_in[8];
    const float* Wl = (const float*)d_in[9];
    const float* bl = (const float*)d_in[10];
    float* out = (float*)d_out;

    void* p;
    cudaGetSymbolAddress(&p, g_xb);    __nv_bfloat16* xb    = (__nv_bfloat16*)p;
    cudaGetSymbolAddress(&p, g_hnode); __nv_bfloat16* hnode = (__nv_bfloat16*)p;
    cudaGetSymbolAddress(&p, g_grow);  __nv_bfloat16* grow  = (__nv_bfloat16*)p;
    cudaGetSymbolAddress(&p, g_gcol);  __nv_bfloat16* gcol  = (__nv_bfloat16*)p;
    cudaGetSymbolAddress(&p, g_eab);   __nv_bfloat16* eab   = (__nv_bfloat16*)p;
    cudaGetSymbolAddress(&p, g_h0);    __nv_bfloat16* h0p   = (__nv_bfloat16*)p;
    cudaGetSymbolAddress(&p, g_Bx);    __nv_bfloat16* Bx    = (__nv_bfloat16*)p;
    cudaGetSymbolAddress(&p, g_B0a);   __nv_bfloat16* B0a   = (__nv_bfloat16*)p;
    cudaGetSymbolAddress(&p, g_B0b);   __nv_bfloat16* B0b   = (__nv_bfloat16*)p;
    cudaGetSymbolAddress(&p, g_B0c);   __nv_bfloat16* B0c   = (__nv_bfloat16*)p;
    cudaGetSymbolAddress(&p, g_Bm);    __nv_bfloat16* Bm    = (__nv_bfloat16*)p;

    constexpr int SMEM = 65536;
    constexpr int FSMEM = 98304 + 8192 + 3072 + 16;   // 109,584
    cudaFuncSetAttribute(gemm_mma<256, 128, true,  true,  false>, cudaFuncAttributeMaxDynamicSharedMemorySize, SMEM);
    cudaFuncSetAttribute(gemm_mma<128, 256, false, false, true >, cudaFuncAttributeMaxDynamicSharedMemorySize, SMEM);
    cudaFuncSetAttribute(gemm_mma<64,  256, false, true,  false>, cudaFuncAttributeMaxDynamicSharedMemorySize, SMEM);
    cudaFuncSetAttribute(fused_mid, cudaFuncAttributeMaxDynamicSharedMemorySize, FSMEM);

    // 1: all prep (conversions + weight images + idx detect)
    prep_everything<<<8192, 256>>>(x, ea, Wx, W0, Wm, (const unsigned*)ei);
    // 2: node MLP: h_node = leaky(x @ Wx + bx)
    gemm_mma<256, 128, true, true, false><<<dim3(NNODES / 128, 1, 1), 256, SMEM>>>(
        xb, Bx, nullptr, bx, hnode, nullptr);
    // 3: node-level edge-GEMM precompute: grow = h@W0a, gcol = h@W0b (one dual launch)
    gemm_mma<128, 256, false, false, true><<<dim3(NNODES / 128, 2, 2), 256, SMEM>>>(
        hnode, B0a, B0b, nullptr, grow, gcol);
    // 4: edge-attr part (+b0): h0p = ea @ W0c + b0
    gemm_mma<64, 256, false, true, false><<<dim3(NEDGES / 128, 2, 1), 256, SMEM>>>(
        eab, B0c, nullptr, b0, h0p, nullptr);
    // 5: gather + combine + leaky (in place on h0p)
    gather_combine<<<NEDGES / 64, 256>>>(ei, grow, gcol, h0p);
    // 6: fused: 8 hidden layers + head + log_softmax   (<- ncu capture target)
    fused_mid<<<NEDGES / 128, 256, FSMEM>>>(h0p, Bm, bm, Wl, bl, out);
}

// round 6
// speedup vs baseline: 1.2253x; 1.2253x over previous
#include <cuda_runtime.h>
#include <cuda_bf16.h>
#include <cstdint>

#define NNODES 65536
#define NEDGES 262144

// ============================ device scratch ============================
__device__ __align__(256) __nv_bfloat16 g_xb   [NNODES * 256];
__device__ __align__(256) __nv_bfloat16 g_hnode[NNODES * 128];
__device__ __align__(256) __nv_bfloat16 g_grow [NNODES * 256];
__device__ __align__(256) __nv_bfloat16 g_gcol [NNODES * 256];
__device__ __align__(256) __nv_bfloat16 g_h0   [(size_t)NEDGES * 256];
// weight images, [NOUT][K] bf16 row-major (k contiguous) == B col-major for mma row.col
__device__ __align__(256) __nv_bfloat16 g_Bx [128 * 256];
__device__ __align__(256) __nv_bfloat16 g_B0a[256 * 128];
__device__ __align__(256) __nv_bfloat16 g_B0b[256 * 128];
__device__ __align__(256) __nv_bfloat16 g_Bm [8][256 * 256];
__device__ int g_idx64;

// ============================ PTX helpers (base PTX only) ============================
__device__ __forceinline__ uint32_t smem_u32(const void* p) {
    uint32_t a;
    asm("{ .reg .u64 t; cvta.to.shared.u64 t, %1; cvt.u32.u64 %0, t; }" : "=r"(a) : "l"(p));
    return a;
}
__device__ __forceinline__ void cp16(uint32_t dst, const void* src) {
    asm volatile("cp.async.cg.shared.global [%0], [%1], 16;" :: "r"(dst), "l"(src));
}
__device__ __forceinline__ void cp_commit() {
    asm volatile("cp.async.commit_group;" ::: "memory");
}
template <int N>
__device__ __forceinline__ void cp_wait() {
    asm volatile("cp.async.wait_group %0;" :: "n"(N) : "memory");
}
__device__ __forceinline__ void ldm_x4(uint32_t* r, uint32_t addr) {
    asm volatile("ldmatrix.sync.aligned.m8n8.x4.shared.b16 {%0,%1,%2,%3}, [%4];"
                 : "=r"(r[0]), "=r"(r[1]), "=r"(r[2]), "=r"(r[3]) : "r"(addr));
}
__device__ __forceinline__ void ldm_x2(uint32_t* r, uint32_t addr) {
    asm volatile("ldmatrix.sync.aligned.m8n8.x2.shared.b16 {%0,%1}, [%2];"
                 : "=r"(r[0]), "=r"(r[1]) : "r"(addr));
}
__device__ __forceinline__ void mma_bf16(float* c, const uint32_t* a, const uint32_t* b) {
    asm volatile(
        "mma.sync.aligned.m16n8k16.row.col.f32.bf16.bf16.f32 "
        "{%0,%1,%2,%3}, {%4,%5,%6,%7}, {%8,%9}, {%0,%1,%2,%3};"
        : "+f"(c[0]), "+f"(c[1]), "+f"(c[2]), "+f"(c[3])
        : "r"(a[0]), "r"(a[1]), "r"(a[2]), "r"(a[3]), "r"(b[0]), "r"(b[1]));
}

// ============================ prep kernels ============================
__global__ void detect_idx64(const unsigned* __restrict__ ei) {
    if (threadIdx.x == 0 && blockIdx.x == 0) {
        int is64 = 1;
        for (int i = 0; i < 512; i++)
            if (ei[2 * i + 1] != 0u) { is64 = 0; break; }
        g_idx64 = is64;
    }
}

__global__ void conv_f32_bf16(const float* __restrict__ src, __nv_bfloat16* __restrict__ dst, int n) {
    for (int i = blockIdx.x * blockDim.x + threadIdx.x; i < n; i += gridDim.x * blockDim.x)
        dst[i] = __float2bfloat16(src[i]);
}

// Coalesced transpose: W fp32 [row0+k][n] (ld=ldW) -> Bimg[n][k] bf16 (zero-pad k>=Ksrc).
// block (32,8), grid (NOUT/32, Kpad/32, nlayers)
__global__ void prep_Bt(const float* __restrict__ W, int row0, int ldW, int Ksrc, int Kpad,
                        size_t wlstride, size_t blstride, __nv_bfloat16* __restrict__ B) {
    __shared__ float tile[32][33];
    W += (size_t)blockIdx.z * wlstride;
    B += (size_t)blockIdx.z * blstride;
    const int n0 = blockIdx.x * 32, k0 = blockIdx.y * 32;
    const int tx = threadIdx.x, ty = threadIdx.y;
    #pragma unroll
    for (int r = 0; r < 32; r += 8) {
        int k = k0 + ty + r;
        tile[ty + r][tx] = (k < Ksrc) ? W[(size_t)(row0 + k) * ldW + n0 + tx] : 0.f;
    }
    __syncthreads();
    #pragma unroll
    for (int r = 0; r < 32; r += 8) {
        int n = n0 + ty + r;
        B[(size_t)n * Kpad + k0 + tx] = __float2bfloat16(tile[tx][ty + r]);
    }
}

// ============================ generic HMMA GEMM (prep stages) ============================
template <int K, int NOUT, bool LEAKY, bool HASBIAS>
__global__ void __launch_bounds__(256)
gemm_mma(const __nv_bfloat16* __restrict__ A, const __nv_bfloat16* __restrict__ B,
         const float* __restrict__ bias, __nv_bfloat16* __restrict__ Out) {
    static_assert(K % 64 == 0, "");
    constexpr int KT = K / 64;
    extern __shared__ char smem[];
    const uint32_t sb = smem_u32(smem);
    constexpr uint32_t STAGE = 32768, BOFF = 16384;

    const int tid = threadIdx.x;
    const int lane = tid & 31, warp = tid >> 5;
    const int warp_m = warp & 1;
    const int warp_n = warp >> 1;
    const size_t m0 = (size_t)blockIdx.x * 128;
    const int n0 = blockIdx.y * 128;

    float acc[4][4][4];
    #pragma unroll
    for (int i = 0; i < 4; i++)
        #pragma unroll
        for (int j = 0; j < 4; j++)
            #pragma unroll
            for (int q = 0; q < 4; q++) acc[i][j][q] = 0.f;

    auto load_stage = [&](int stage, int kt) {
        const uint32_t base = sb + stage * STAGE;
        #pragma unroll
        for (int i = 0; i < 4; i++) {
            int idx = tid + i * 256;
            int r = idx >> 3, c8 = idx & 7;
            uint32_t dst = base + r * 128 + (((c8 ^ (r & 7))) << 4);
            cp16(dst, A + (m0 + r) * K + kt * 64 + c8 * 8);
        }
        #pragma unroll
        for (int i = 0; i < 4; i++) {
            int idx = tid + i * 256;
            int r = idx >> 3, c8 = idx & 7;
            uint32_t dst = base + BOFF + r * 128 + (((c8 ^ (r & 7))) << 4);
            cp16(dst, B + (size_t)(n0 + r) * K + kt * 64 + c8 * 8);
        }
    };

    load_stage(0, 0);
    cp_commit();

    for (int kt = 0; kt < KT; kt++) {
        if (kt + 1 < KT) { load_stage((kt + 1) & 1, kt + 1); cp_commit(); cp_wait<1>(); }
        else             { cp_wait<0>(); }
        __syncthreads();

        const uint32_t abase = sb + (kt & 1) * STAGE;
        const uint32_t bbase = abase + BOFF;
        #pragma unroll
        for (int ks = 0; ks < 4; ks++) {
            uint32_t af[4][4];
            #pragma unroll
            for (int mi = 0; mi < 4; mi++) {
                int r = warp_m * 64 + mi * 16 + (lane & 15);
                int c8 = ks * 2 + (lane >> 4);
                ldm_x4(af[mi], abase + r * 128 + ((c8 ^ (r & 7)) << 4));
            }
            uint32_t bf2[4][2];
            #pragma unroll
            for (int ni = 0; ni < 4; ni++) {
                int r = warp_n * 32 + ni * 8 + (lane & 7);
                int c8 = ks * 2 + ((lane >> 3) & 1);
                ldm_x2(bf2[ni], bbase + r * 128 + ((c8 ^ (r & 7)) << 4));
            }
            #pragma unroll
            for (int mi = 0; mi < 4; mi++)
                #pragma unroll
                for (int ni = 0; ni < 4; ni++)
                    mma_bf16(acc[mi][ni], af[mi], bf2[ni]);
        }
        __syncthreads();
    }

    const int g = lane >> 2;
    #pragma unroll
    for (int ni = 0; ni < 4; ni++) {
        const int col = n0 + warp_n * 32 + ni * 8 + ((lane & 3) << 1);
        float bb0 = 0.f, bb1 = 0.f;
        if (HASBIAS) { bb0 = __ldg(bias + col); bb1 = __ldg(bias + col + 1); }
        #pragma unroll
        for (int mi = 0; mi < 4; mi++) {
            const size_t r0 = m0 + warp_m * 64 + mi * 16 + g;
            float v0 = acc[mi][ni][0] + bb0, v1 = acc[mi][ni][1] + bb1;
            float v2 = acc[mi][ni][2] + bb0, v3 = acc[mi][ni][3] + bb1;
            if (LEAKY) {
                v0 = v0 >= 0.f ? v0 : 0.01f * v0;  v1 = v1 >= 0.f ? v1 : 0.01f * v1;
                v2 = v2 >= 0.f ? v2 : 0.01f * v2;  v3 = v3 >= 0.f ? v3 : 0.01f * v3;
            }
            __nv_bfloat162 p0 = __floats2bfloat162_rn(v0, v1);
            __nv_bfloat162 p1 = __floats2bfloat162_rn(v2, v3);
            *(uint32_t*)(Out + r0 * NOUT + col)       = *(uint32_t*)&p0;
            *(uint32_t*)(Out + (r0 + 8) * NOUT + col) = *(uint32_t*)&p1;
        }
    }
}

// ============================ gather + ea-matvec + combine ============================
// h0[e] = leaky( ea[e]@W0c + b0 + grow[row[e]] + gcol[col[e]] )
__global__ void __launch_bounds__(256)
gather_combine_ea(const int* __restrict__ ei, const float* __restrict__ ea,
                  const float* __restrict__ W0, const float* __restrict__ b0,
                  const __nv_bfloat16* __restrict__ gr, const __nv_bfloat16* __restrict__ gc,
                  __nv_bfloat16* __restrict__ h0) {
    __shared__ float sea[64][16];
    __shared__ int srow[64], scol[64];
    const int t = threadIdx.x;
    const long e0 = (long)blockIdx.x * 64;
    const int is64 = g_idx64;
    if (t < 64) {
        long e = e0 + t;
        if (is64) { srow[t] = ei[2 * e]; scol[t] = ei[2 * (NEDGES + e)]; }
        else      { srow[t] = ei[e];     scol[t] = ei[NEDGES + e]; }
    }
    {   // edge_attr tile: 64 x 16 fp32, fully coalesced
        int e = t >> 2, k = (t & 3) * 4;
        *(float4*)&sea[e][k] = *(const float4*)(ea + (e0 + e) * 16 + k);
    }
    const int cp = t & 127;   // column pair this thread owns
    float2 w[16];             // W0c[:, 2cp..2cp+1] in registers (rows 256..271 of W0)
    #pragma unroll
    for (int k = 0; k < 16; k++)
        w[k] = *(const float2*)(W0 + (size_t)(256 + k) * 256 + 2 * cp);
    const float2 bb = *(const float2*)(b0 + 2 * cp);
    __syncthreads();

    const int eo = t >> 7;
    for (int i = eo; i < 64; i += 2) {
        float v0 = bb.x, v1 = bb.y;
        #pragma unroll
        for (int k = 0; k < 16; k++) {
            float s = sea[i][k];
            v0 += s * w[k].x;
            v1 += s * w[k].y;
        }
        const __nv_bfloat162 gv = ((const __nv_bfloat162*)(gr + (size_t)srow[i] * 256))[cp];
        const __nv_bfloat162 cv = ((const __nv_bfloat162*)(gc + (size_t)scol[i] * 256))[cp];
        float2 gb = __bfloat1622float2(gv);
        float2 cb = __bfloat1622float2(cv);
        v0 += gb.x + cb.x;
        v1 += gb.y + cb.y;
        v0 = v0 >= 0.f ? v0 : 0.01f * v0;
        v1 = v1 >= 0.f ? v1 : 0.01f * v1;
        ((__nv_bfloat162*)(h0 + (size_t)(e0 + i) * 256))[cp] = __floats2bfloat162_rn(v0, v1);
    }
}

// ============================ fused 8 mid layers + head (R3 structure) ============================
__global__ void __launch_bounds__(256, 1)
fused_mid(const __nv_bfloat16* __restrict__ h0, const __nv_bfloat16* __restrict__ Bm,
          const float* __restrict__ bm, const float* __restrict__ Wl,
          const float* __restrict__ bl, float* __restrict__ out) {
    extern __shared__ char smem[];
    const uint32_t sb = smem_u32(smem);
    constexpr uint32_t RINGOFF = 65536;               // A tile: [0, 64KB)
    constexpr uint32_t BIASOFF = 65536 + 131072;      // ring: 4 x 32KB
    float* sbias = (float*)(smem + BIASOFF);          // 8*256 fp32
    float* sWl   = (float*)(smem + BIASOFF + 8192);   // 256*3 fp32
    float* sbl   = (float*)(smem + BIASOFF + 8192 + 3072);

    const int tid = threadIdx.x, lane = tid & 31, warp = tid >> 5;
    const size_t m0 = (size_t)blockIdx.x * 128;

    for (int i = tid; i < 2048; i += 256) sbias[i] = bm[i];
    for (int i = tid; i < 768; i += 256) sWl[i] = Wl[i];
    if (tid < 3) sbl[tid] = bl[tid];

    // B ring loader: step s -> layer s>>2, k-half s&3, slot s&3
    auto loadB = [&](int s) {
        const uint32_t base = sb + RINGOFF + (uint32_t)(s & 3) * 32768u;
        const __nv_bfloat16* src = Bm + (size_t)(s >> 2) * 65536 + (s & 3) * 64;
        #pragma unroll
        for (int i = 0; i < 8; i++) {
            int idx = tid + i * 256;
            int r = idx >> 3, c8 = idx & 7;
            cp16(base + r * 128 + ((c8 ^ (r & 7)) << 4), src + (size_t)r * 256 + c8 * 8);
        }
    };
    loadB(0); cp_commit();
    loadB(1); cp_commit();

    // A tile (h0, 128x256) -> smem as 4 chunks of [128][64]
    #pragma unroll
    for (int kc = 0; kc < 4; kc++)
        #pragma unroll
        for (int i = 0; i < 4; i++) {
            int idx = tid + i * 256;
            int r = idx >> 3, c8 = idx & 7;
            cp16(sb + kc * 16384 + r * 128 + ((c8 ^ (r & 7)) << 4),
                 h0 + (m0 + r) * 256 + kc * 64 + c8 * 8);
        }
    cp_commit();
    cp_wait<0>();
    __syncthreads();

    // ldmatrix A -> packed activation fragments pa[32][2]
    uint32_t pa[32][2];
    #pragma unroll
    for (int s = 0; s < 16; s++) {
        int rr = warp * 16 + (lane & 15);
        int cc = (s & 3) * 2 + (lane >> 4);
        uint32_t f[4];
        ldm_x4(f, sb + (s >> 2) * 16384 + rr * 128 + ((cc ^ (rr & 7)) << 4));
        pa[2 * s][0] = f[0]; pa[2 * s][1] = f[1];
        pa[2 * s + 1][0] = f[2]; pa[2 * s + 1][1] = f[3];
    }

    const int j = lane & 3;
    for (int l = 0; l < 8; ++l) {
        float acc[32][4];
        const float2* b2 = (const float2*)(sbias + (l << 8));
        #pragma unroll
        for (int ni = 0; ni < 32; ni++) {
            float2 bb = b2[4 * ni + j];
            acc[ni][0] = bb.x; acc[ni][1] = bb.y; acc[ni][2] = bb.x; acc[ni][3] = bb.y;
        }
        #pragma unroll
        for (int kh = 0; kh < 4; kh++) {
            const int s = l * 4 + kh;
            cp_wait<1>();
            __syncthreads();
            if (s + 2 < 32) loadB(s + 2);
            cp_commit();
            const uint32_t bbase = sb + RINGOFF + (uint32_t)(s & 3) * 32768u;
            const int rr_lo = ((lane >> 4) << 3) + (lane & 7);
            #pragma unroll
            for (int ksl = 0; ksl < 4; ksl++) {
                const int ai = kh * 8 + ksl * 2;
                uint32_t a[4] = {pa[ai][0], pa[ai][1], pa[ai + 1][0], pa[ai + 1][1]};
                const int cc = ksl * 2 + ((lane >> 3) & 1);
                #pragma unroll
                for (int np = 0; np < 16; np++) {
                    int rr = np * 16 + rr_lo;
                    uint32_t bf[4];
                    ldm_x4(bf, bbase + rr * 128 + ((cc ^ (rr & 7)) << 4));
                    mma_bf16(acc[2 * np], a, bf);
                    mma_bf16(acc[2 * np + 1], a, bf + 2);
                }
            }
        }
        #pragma unroll
        for (int ni = 0; ni < 32; ni++) {
            float v0 = acc[ni][0], v1 = acc[ni][1], v2 = acc[ni][2], v3 = acc[ni][3];
            v0 = v0 >= 0.f ? v0 : 0.01f * v0;  v1 = v1 >= 0.f ? v1 : 0.01f * v1;
            v2 = v2 >= 0.f ? v2 : 0.01f * v2;  v3 = v3 >= 0.f ? v3 : 0.01f * v3;
            __nv_bfloat162 p0 = __floats2bfloat162_rn(v0, v1);
            __nv_bfloat162 p1 = __floats2bfloat162_rn(v2, v3);
            pa[ni][0] = *(uint32_t*)&p0;
            pa[ni][1] = *(uint32_t*)&p1;
        }
    }

    // ---- fused head: logits = h @ Wlast + blast, then log_softmax ----
    float a3[2][3] = {{0.f, 0.f, 0.f}, {0.f, 0.f, 0.f}};
    #pragma unroll
    for (int t = 0; t < 32; t++) {
        float2 x = __bfloat1622float2(*(__nv_bfloat162*)&pa[t][0]);
        float2 y = __bfloat1622float2(*(__nv_bfloat162*)&pa[t][1]);
        const int c0 = 8 * t + 2 * j;
        float w00 = sWl[c0 * 3 + 0], w01 = sWl[c0 * 3 + 1], w02 = sWl[c0 * 3 + 2];
        float w10 = sWl[c0 * 3 + 3], w11 = sWl[c0 * 3 + 4], w12 = sWl[c0 * 3 + 5];
        a3[0][0] += x.x * w00 + x.y * w10;
        a3[0][1] += x.x * w01 + x.y * w11;
        a3[0][2] += x.x * w02 + x.y * w12;
        a3[1][0] += y.x * w00 + y.y * w10;
        a3[1][1] += y.x * w01 + y.y * w11;
        a3[1][2] += y.x * w02 + y.y * w12;
    }
    #pragma unroll
    for (int off = 1; off <= 2; off <<= 1) {
        #pragma unroll
        for (int r = 0; r < 2; r++)
            #pragma unroll
            for (int c = 0; c < 3; c++)
                a3[r][c] += __shfl_xor_sync(0xFFFFFFFFu, a3[r][c], off);
    }
    if (j == 0) {
        const int g = lane >> 2;
        const float bb0 = sbl[0], bb1 = sbl[1], bb2 = sbl[2];
        #pragma unroll
        for (int r = 0; r < 2; r++) {
            size_t e = m0 + warp * 16 + g + 8 * r;
            float l0 = a3[r][0] + bb0, l1 = a3[r][1] + bb1, l2 = a3[r][2] + bb2;
            float m = fmaxf(l0, fmaxf(l1, l2));
            float ls = m + logf(expf(l0 - m) + expf(l1 - m) + expf(l2 - m));
            out[e * 3 + 0] = l0 - ls;
            out[e * 3 + 1] = l1 - ls;
            out[e * 3 + 2] = l2 - ls;
        }
    }
}

// ============================ host ============================
extern "C" void kernel_launch(void* const* d_in, const int* in_sizes, int n_in,
                              void* d_out, int out_size) {
    const float* x  = (const float*)d_in[0];
    const int*   ei = (const int*)d_in[1];
    const float* ea = (const float*)d_in[2];
    const float* Wx = (const float*)d_in[3];
    const float* bx = (const float*)d_in[4];
    const float* W0 = (const float*)d_in[5];
    const float* b0 = (const float*)d_in[6];
    const float* Wm = (const float*)d_in[7];
    const float* bm = (const float*)d_in[8];
    const float* Wl = (const float*)d_in[9];
    const float* bl = (const float*)d_in[10];
    float* out = (float*)d_out;

    void* p;
    cudaGetSymbolAddress(&p, g_xb);    __nv_bfloat16* xb    = (__nv_bfloat16*)p;
    cudaGetSymbolAddress(&p, g_hnode); __nv_bfloat16* hnode = (__nv_bfloat16*)p;
    cudaGetSymbolAddress(&p, g_grow);  __nv_bfloat16* grow  = (__nv_bfloat16*)p;
    cudaGetSymbolAddress(&p, g_gcol);  __nv_bfloat16* gcol  = (__nv_bfloat16*)p;
    cudaGetSymbolAddress(&p, g_h0);    __nv_bfloat16* h0p   = (__nv_bfloat16*)p;
    cudaGetSymbolAddress(&p, g_Bx);    __nv_bfloat16* Bx    = (__nv_bfloat16*)p;
    cudaGetSymbolAddress(&p, g_B0a);   __nv_bfloat16* B0a   = (__nv_bfloat16*)p;
    cudaGetSymbolAddress(&p, g_B0b);   __nv_bfloat16* B0b   = (__nv_bfloat16*)p;
    cudaGetSymbolAddress(&p, g_Bm);    __nv_bfloat16* Bm    = (__nv_bfloat16*)p;

    constexpr int SMEM = 65536;
    constexpr int FSMEM = 65536 + 131072 + 8192 + 3072 + 16;   // 207,904
    cudaFuncSetAttribute(gemm_mma<256, 128, true,  true >, cudaFuncAttributeMaxDynamicSharedMemorySize, SMEM);
    cudaFuncSetAttribute(gemm_mma<128, 256, false, false>, cudaFuncAttributeMaxDynamicSharedMemorySize, SMEM);
    cudaFuncSetAttribute(fused_mid, cudaFuncAttributeMaxDynamicSharedMemorySize, FSMEM);

    // --- prep ---
    detect_idx64<<<1, 32>>>((const unsigned*)ei);
    conv_f32_bf16<<<4096, 256>>>(x, xb, NNODES * 256);
    prep_Bt<<<dim3(4, 8, 1), dim3(32, 8)>>>(Wx, 0, 128, 256, 256, 0, 0, Bx);      // Bx [128][256]
    prep_Bt<<<dim3(8, 4, 1), dim3(32, 8)>>>(W0, 0,   256, 128, 128, 0, 0, B0a);   // B0a [256][128]
    prep_Bt<<<dim3(8, 4, 1), dim3(32, 8)>>>(W0, 128, 256, 128, 128, 0, 0, B0b);   // B0b [256][128]
    prep_Bt<<<dim3(8, 8, 8), dim3(32, 8)>>>(Wm, 0, 256, 256, 256, 65536, 65536, Bm); // Bm x8

    // --- node MLP: h_node = leaky(x @ Wx + bx) ---
    gemm_mma<256, 128, true, true><<<dim3(NNODES / 128, 1), 256, SMEM>>>(xb, Bx, bx, hnode);
    // --- node-level edge-GEMM precompute ---
    gemm_mma<128, 256, false, false><<<dim3(NNODES / 128, 2), 256, SMEM>>>(hnode, B0a, nullptr, grow);
    gemm_mma<128, 256, false, false><<<dim3(NNODES / 128, 2), 256, SMEM>>>(hnode, B0b, nullptr, gcol);
    // --- gather + ea matvec + combine + leaky -> h0 ---
    gather_combine_ea<<<NEDGES / 64, 256>>>(ei, ea, W0, b0, grow, gcol, h0p);
    // --- fused: 8 hidden layers + head + log_softmax ---
    fused_mid<<<NEDGES / 128, 256, FSMEM>>>(h0p, Bm, bm, Wl, bl, out);
}